// round 1
// baseline (speedup 1.0000x reference)
#include <cuda_runtime.h>
#include <math.h>

// ---------------------------------------------------------------------------
// Problem shapes (fixed by the dataset): B=4096, N=8192, D=1024, dims 1024/512/256
// Static scratch (allocation inside kernel_launch is forbidden).
// ---------------------------------------------------------------------------
#define MAXD 1024

__device__ float g_sum[MAXD];
__device__ float g_sumsq[MAXD];
__device__ float g_a[MAXD];       // per-input-column scale  = gamma * rsqrt(var+eps)
__device__ float g_dd[MAXD];      // per-input-column shift  = beta - mean * a
__device__ float g_bias2[MAXD];   // folded bias = b + d @ W
__device__ float g_k2[8192];
__device__ float g_bufA[8192 * 1024];
__device__ float g_bufB[8192 * 1024];
__device__ float g_q[4096 * 256];
__device__ float g_kf[8192 * 256];
__device__ float g_sim[(size_t)4096 * 8192];

// ---------------------------------------------------------------------------
// Stats kernels
// ---------------------------------------------------------------------------
__global__ void zero_stats(int Din) {
    int i = blockIdx.x * blockDim.x + threadIdx.x;
    if (i < Din) { g_sum[i] = 0.f; g_sumsq[i] = 0.f; }
}

__global__ void colstats(const float* __restrict__ X, int R, int Din) {
    int c = blockIdx.x * blockDim.x + threadIdx.x;
    if (c >= Din) return;
    int chunk = R / gridDim.y;
    int r0 = blockIdx.y * chunk;
    float s = 0.f, s2 = 0.f;
    for (int r = r0; r < r0 + chunk; ++r) {
        float v = X[(size_t)r * Din + c];
        s += v;
        s2 = fmaf(v, v, s2);
    }
    atomicAdd(&g_sum[c], s);
    atomicAdd(&g_sumsq[c], s2);
}

__global__ void finalize_stats(int R, int Din,
                               const float* __restrict__ gam,
                               const float* __restrict__ bet) {
    int c = blockIdx.x * blockDim.x + threadIdx.x;
    if (c >= Din) return;
    float inv = 1.0f / (float)R;
    float mean = g_sum[c] * inv;
    float var = g_sumsq[c] * inv - mean * mean;
    float a = gam[c] * rsqrtf(var + 1e-5f);
    g_a[c] = a;
    g_dd[c] = bet[c] - mean * a;
}

__global__ void init_bias2(const float* __restrict__ b, int Dout) {
    int o = blockIdx.x * blockDim.x + threadIdx.x;
    if (o < Dout) g_bias2[o] = b[o];
}

// bias2[o] += sum_c d[c] * W[c, o]  (accumulated over 128-wide c-chunks)
__global__ void bias2acc(const float* __restrict__ W, int Din, int Dout) {
    int o = blockIdx.x * 128 + threadIdx.x;
    int c0 = blockIdx.y * 128;
    float s = 0.f;
#pragma unroll 4
    for (int c = 0; c < 128; ++c)
        s = fmaf(g_dd[c0 + c], W[(size_t)(c0 + c) * Dout + o], s);
    atomicAdd(&g_bias2[o], s);
}

// ---------------------------------------------------------------------------
// Fused GEMM: C[R,Dout] = tanh( (A * a_col) @ W + bias2 )
// A row-major [R,Din], W row-major [Din,Dout]. All dims multiples of 128/16.
// Tile 128x128x16, 256 threads, 8x8 microtile.
// ---------------------------------------------------------------------------
__global__ __launch_bounds__(256) void gemm_bn_tanh(
    const float* __restrict__ A, const float* __restrict__ W,
    float* __restrict__ C, int Din, int Dout)
{
    __shared__ float As[16][132];
    __shared__ float Ws[16][132];
    const int tid = threadIdx.x;
    const int tm = tid >> 4, tn = tid & 15;
    const int m0 = blockIdx.y * 128, n0 = blockIdx.x * 128;

    float acc[8][8];
#pragma unroll
    for (int i = 0; i < 8; ++i)
#pragma unroll
        for (int j = 0; j < 8; ++j) acc[i][j] = 0.f;

    for (int k0 = 0; k0 < Din; k0 += 16) {
#pragma unroll
        for (int l = 0; l < 8; ++l) {
            int idx = tid + l * 256;
            int m = idx >> 4, k = idx & 15;
            As[k][m] = A[(size_t)(m0 + m) * Din + (k0 + k)] * g_a[k0 + k];
        }
#pragma unroll
        for (int l = 0; l < 8; ++l) {
            int idx = tid + l * 256;
            int k = idx >> 7, n = idx & 127;
            Ws[k][n] = W[(size_t)(k0 + k) * Dout + (n0 + n)];
        }
        __syncthreads();
#pragma unroll
        for (int kk = 0; kk < 16; ++kk) {
            float av[8], bv[8];
            *(float4*)&av[0] = *(const float4*)&As[kk][tm * 8];
            *(float4*)&av[4] = *(const float4*)&As[kk][tm * 8 + 4];
            *(float4*)&bv[0] = *(const float4*)&Ws[kk][tn * 8];
            *(float4*)&bv[4] = *(const float4*)&Ws[kk][tn * 8 + 4];
#pragma unroll
            for (int i = 0; i < 8; ++i)
#pragma unroll
                for (int j = 0; j < 8; ++j)
                    acc[i][j] = fmaf(av[i], bv[j], acc[i][j]);
        }
        __syncthreads();
    }

#pragma unroll
    for (int i = 0; i < 8; ++i) {
        int m = m0 + tm * 8 + i;
        int nb = n0 + tn * 8;
        float4 o0, o1;
        o0.x = tanhf(acc[i][0] + g_bias2[nb + 0]);
        o0.y = tanhf(acc[i][1] + g_bias2[nb + 1]);
        o0.z = tanhf(acc[i][2] + g_bias2[nb + 2]);
        o0.w = tanhf(acc[i][3] + g_bias2[nb + 3]);
        o1.x = tanhf(acc[i][4] + g_bias2[nb + 4]);
        o1.y = tanhf(acc[i][5] + g_bias2[nb + 5]);
        o1.z = tanhf(acc[i][6] + g_bias2[nb + 6]);
        o1.w = tanhf(acc[i][7] + g_bias2[nb + 7]);
        *(float4*)&C[(size_t)m * Dout + nb] = o0;
        *(float4*)&C[(size_t)m * Dout + nb + 4] = o1;
    }
}

// ---------------------------------------------------------------------------
// k2[row] = sum of squares of k row (Kd=256, block=256)
// ---------------------------------------------------------------------------
__global__ void rowsq(const float* __restrict__ Kf, int Kd) {
    __shared__ float red[256];
    int row = blockIdx.x, t = threadIdx.x;
    float v = (t < Kd) ? Kf[(size_t)row * Kd + t] : 0.f;
    red[t] = v * v;
    __syncthreads();
    for (int s = 128; s > 0; s >>= 1) {
        if (t < s) red[t] += red[t + s];
        __syncthreads();
    }
    if (t == 0) g_k2[row] = red[0];
}

// ---------------------------------------------------------------------------
// sim[m,n] = 2 * (q_m . k_n) - k2[n]   (q2 dropped: softmax-row invariant)
// q [M,Kd] row-major, Kf [N,Kd] row-major.
// ---------------------------------------------------------------------------
__global__ __launch_bounds__(256) void gemm_sim(
    const float* __restrict__ Q, const float* __restrict__ Kf,
    float* __restrict__ S, int Kd, int N)
{
    __shared__ float As[16][132];
    __shared__ float Bs[16][132];
    const int tid = threadIdx.x;
    const int tm = tid >> 4, tn = tid & 15;
    const int m0 = blockIdx.y * 128, n0 = blockIdx.x * 128;

    float acc[8][8];
#pragma unroll
    for (int i = 0; i < 8; ++i)
#pragma unroll
        for (int j = 0; j < 8; ++j) acc[i][j] = 0.f;

    for (int k0 = 0; k0 < Kd; k0 += 16) {
#pragma unroll
        for (int l = 0; l < 8; ++l) {
            int idx = tid + l * 256;
            int m = idx >> 4, k = idx & 15;
            As[k][m] = Q[(size_t)(m0 + m) * Kd + (k0 + k)];
        }
#pragma unroll
        for (int l = 0; l < 8; ++l) {
            int idx = tid + l * 256;
            int n = idx >> 4, k = idx & 15;
            Bs[k][n] = Kf[(size_t)(n0 + n) * Kd + (k0 + k)];
        }
        __syncthreads();
#pragma unroll
        for (int kk = 0; kk < 16; ++kk) {
            float av[8], bv[8];
            *(float4*)&av[0] = *(const float4*)&As[kk][tm * 8];
            *(float4*)&av[4] = *(const float4*)&As[kk][tm * 8 + 4];
            *(float4*)&bv[0] = *(const float4*)&Bs[kk][tn * 8];
            *(float4*)&bv[4] = *(const float4*)&Bs[kk][tn * 8 + 4];
#pragma unroll
            for (int i = 0; i < 8; ++i)
#pragma unroll
                for (int j = 0; j < 8; ++j)
                    acc[i][j] = fmaf(av[i], bv[j], acc[i][j]);
        }
        __syncthreads();
    }

#pragma unroll
    for (int i = 0; i < 8; ++i) {
        int m = m0 + tm * 8 + i;
        int nb = n0 + tn * 8;
        float4 o0, o1;
        o0.x = 2.f * acc[i][0] - g_k2[nb + 0];
        o0.y = 2.f * acc[i][1] - g_k2[nb + 1];
        o0.z = 2.f * acc[i][2] - g_k2[nb + 2];
        o0.w = 2.f * acc[i][3] - g_k2[nb + 3];
        o1.x = 2.f * acc[i][4] - g_k2[nb + 4];
        o1.y = 2.f * acc[i][5] - g_k2[nb + 5];
        o1.z = 2.f * acc[i][6] - g_k2[nb + 6];
        o1.w = 2.f * acc[i][7] - g_k2[nb + 7];
        *(float4*)&S[(size_t)m * N + nb] = o0;
        *(float4*)&S[(size_t)m * N + nb + 4] = o1;
    }
}

// ---------------------------------------------------------------------------
// out[row] = clip( sum_j softmax(sim[row,:])_j * y[j], 0, 1 )
// One block per row, row cached in dynamic smem (N*4 = 32KB).
// ---------------------------------------------------------------------------
__global__ void softmax_out(const float* __restrict__ sim,
                            const float* __restrict__ y,
                            float* __restrict__ out, int N)
{
    extern __shared__ float srow[];
    __shared__ float red[256];
    int row = blockIdx.x, t = threadIdx.x;
    const float* s = sim + (size_t)row * N;

    float lmax = -3.4e38f;
    for (int j = t; j < N; j += 256) {
        float v = s[j];
        srow[j] = v;
        lmax = fmaxf(lmax, v);
    }
    red[t] = lmax;
    __syncthreads();
    for (int st = 128; st > 0; st >>= 1) {
        if (t < st) red[t] = fmaxf(red[t], red[t + st]);
        __syncthreads();
    }
    float m = red[0];
    __syncthreads();

    float lsum = 0.f, lw = 0.f;
    for (int j = t; j < N; j += 256) {
        float e = __expf(srow[j] - m);
        lsum += e;
        lw = fmaf(e, y[j], lw);
    }
    red[t] = lsum;
    __syncthreads();
    for (int st = 128; st > 0; st >>= 1) {
        if (t < st) red[t] += red[t + st];
        __syncthreads();
    }
    float tot = red[0];
    __syncthreads();
    red[t] = lw;
    __syncthreads();
    for (int st = 128; st > 0; st >>= 1) {
        if (t < st) red[t] += red[t + st];
        __syncthreads();
    }
    if (t == 0) {
        float r = red[0] / tot;
        out[row] = fminf(fmaxf(r, 0.f), 1.f);
    }
}

// ---------------------------------------------------------------------------
// Host launcher
// ---------------------------------------------------------------------------
extern "C" void kernel_launch(void* const* d_in, const int* in_sizes, int n_in,
                              void* d_out, int out_size)
{
    const float* x   = (const float*)d_in[0];
    const float* xn  = (const float*)d_in[1];
    const float* y   = (const float*)d_in[2];
    const float* W1  = (const float*)d_in[3];
    const float* b1  = (const float*)d_in[4];
    const float* gm1 = (const float*)d_in[5];
    const float* be1 = (const float*)d_in[6];
    const float* W2  = (const float*)d_in[7];
    const float* b2  = (const float*)d_in[8];
    const float* gm2 = (const float*)d_in[9];
    const float* be2 = (const float*)d_in[10];
    const float* W3  = (const float*)d_in[11];
    const float* b3  = (const float*)d_in[12];
    const float* gm3 = (const float*)d_in[13];
    const float* be3 = (const float*)d_in[14];

    const int D  = in_sizes[5];          // 1024
    const int B  = in_sizes[0] / D;      // 4096
    const int N  = in_sizes[2];          // 8192
    const int D1 = in_sizes[4];          // 1024
    const int D2 = in_sizes[8];          // 512
    const int D3 = in_sizes[12];         // 256

    float *bufA, *bufB, *qp, *kp, *simp;
    cudaGetSymbolAddress((void**)&bufA, g_bufA);
    cudaGetSymbolAddress((void**)&bufB, g_bufB);
    cudaGetSymbolAddress((void**)&qp,   g_q);
    cudaGetSymbolAddress((void**)&kp,   g_kf);
    cudaGetSymbolAddress((void**)&simp, g_sim);

    auto run_layer = [&](const float* X, int R, int Din, int Dout,
                         const float* W, const float* b,
                         const float* gam, const float* bet, float* Y) {
        zero_stats<<<(Din + 255) / 256, 256>>>(Din);
        colstats<<<dim3((Din + 255) / 256, 32), 256>>>(X, R, Din);
        finalize_stats<<<(Din + 255) / 256, 256>>>(R, Din, gam, bet);
        init_bias2<<<(Dout + 255) / 256, 256>>>(b, Dout);
        bias2acc<<<dim3(Dout / 128, Din / 128), 128>>>(W, Din, Dout);
        gemm_bn_tanh<<<dim3(Dout / 128, R / 128), 256>>>(X, W, Y, Din, Dout);
    };

    // q branch
    run_layer(x,    B, D,  D1, W1, b1, gm1, be1, bufA);
    run_layer(bufA, B, D1, D2, W2, b2, gm2, be2, bufB);
    run_layer(bufB, B, D2, D3, W3, b3, gm3, be3, qp);
    // k branch
    run_layer(xn,   N, D,  D1, W1, b1, gm1, be1, bufA);
    run_layer(bufA, N, D1, D2, W2, b2, gm2, be2, bufB);
    run_layer(bufB, N, D2, D3, W3, b3, gm3, be3, kp);

    rowsq<<<N, 256>>>(kp, D3);
    gemm_sim<<<dim3(N / 128, B / 128), 256>>>(qp, kp, simp, D3, N);
    softmax_out<<<B, 256, N * sizeof(float)>>>(simp, y, (float*)d_out, N);
}

// round 3
// speedup vs baseline: 1.7640x; 1.7640x over previous
#include <cuda_runtime.h>
#include <cuda_bf16.h>
#include <math.h>
#include <stdint.h>

// ===========================================================================
// Static scratch (B=4096, N=8192, D<=1024 fixed by dataset)
// ===========================================================================
__device__ float g_sum[1024];
__device__ float g_sumsq[1024];
__device__ float g_a[1024];
__device__ float g_dd[1024];
__device__ float g_bias2[1024];
__device__ float g_k2[8192];
__device__ __nv_bfloat16 g_P1h[8192 * 1024], g_P1l[8192 * 1024];
__device__ __nv_bfloat16 g_P2h[8192 * 1024], g_P2l[8192 * 1024];
__device__ __nv_bfloat16 g_WTh[1024 * 1024], g_WTl[1024 * 1024];
__device__ __nv_bfloat16 g_qh[4096 * 256], g_ql[4096 * 256];
__device__ __nv_bfloat16 g_kh[8192 * 256], g_kl[8192 * 256];
__device__ float g_sim[(size_t)4096 * 8192];

// ===========================================================================
// Small prep kernels
// ===========================================================================
__global__ void zero_stats(int Din) {
    int i = blockIdx.x * blockDim.x + threadIdx.x;
    if (i < Din) { g_sum[i] = 0.f; g_sumsq[i] = 0.f; }
}

__global__ void colstats(const float* __restrict__ X, int R, int Din) {
    int c = blockIdx.x * blockDim.x + threadIdx.x;
    if (c >= Din) return;
    int chunk = R / gridDim.y;
    int r0 = blockIdx.y * chunk;
    float s = 0.f, s2 = 0.f;
    for (int r = r0; r < r0 + chunk; ++r) {
        float v = X[(size_t)r * Din + c];
        s += v; s2 = fmaf(v, v, s2);
    }
    atomicAdd(&g_sum[c], s);
    atomicAdd(&g_sumsq[c], s2);
}

__global__ void colstats_bf(const __nv_bfloat16* __restrict__ hi,
                            const __nv_bfloat16* __restrict__ lo, int R, int Din) {
    int c = blockIdx.x * blockDim.x + threadIdx.x;
    if (c >= Din) return;
    int chunk = R / gridDim.y;
    int r0 = blockIdx.y * chunk;
    float s = 0.f, s2 = 0.f;
    for (int r = r0; r < r0 + chunk; ++r) {
        size_t i = (size_t)r * Din + c;
        float v = __bfloat162float(hi[i]) + __bfloat162float(lo[i]);
        s += v; s2 = fmaf(v, v, s2);
    }
    atomicAdd(&g_sum[c], s);
    atomicAdd(&g_sumsq[c], s2);
}

__global__ void finalize_stats(int R, int Din,
                               const float* __restrict__ gam,
                               const float* __restrict__ bet) {
    int c = blockIdx.x * blockDim.x + threadIdx.x;
    if (c >= Din) return;
    float inv = 1.0f / (float)R;
    float mean = g_sum[c] * inv;
    float var = g_sumsq[c] * inv - mean * mean;
    float a = gam[c] * rsqrtf(var + 1e-5f);
    g_a[c] = a;
    g_dd[c] = bet[c] - mean * a;
}

__global__ void init_bias2(const float* __restrict__ b, int Dout) {
    int o = blockIdx.x * blockDim.x + threadIdx.x;
    if (o < Dout) g_bias2[o] = b[o];
}

__global__ void bias2acc(const float* __restrict__ W, int Din, int Dout) {
    int o = blockIdx.x * 128 + threadIdx.x;
    int c0 = blockIdx.y * 128;
    float s = 0.f;
#pragma unroll 4
    for (int c = 0; c < 128; ++c)
        s = fmaf(g_dd[c0 + c], W[(size_t)(c0 + c) * Dout + o], s);
    atomicAdd(&g_bias2[o], s);
}

// fp32 -> (hi, lo) bf16 split
__global__ void splitf(const float* __restrict__ X,
                       __nv_bfloat16* __restrict__ hi,
                       __nv_bfloat16* __restrict__ lo, int n) {
    int i = blockIdx.x * blockDim.x + threadIdx.x;
    if (i >= n) return;
    float v = X[i];
    __nv_bfloat16 h = __float2bfloat16(v);
    hi[i] = h;
    lo[i] = __float2bfloat16(v - __bfloat162float(h));
}

// WT[n,k] = a[k] * W[k,n], split to bf16 hi/lo; tiled transpose (32x32, 32x8 thr)
__global__ void wprep(const float* __restrict__ W, int Din, int Dout,
                      __nv_bfloat16* __restrict__ WTh, __nv_bfloat16* __restrict__ WTl) {
    __shared__ float tile[32][33];
    int k0 = blockIdx.y * 32, n0 = blockIdx.x * 32;
    int tx = threadIdx.x, ty = threadIdx.y;
    for (int i = ty; i < 32; i += 8)
        tile[i][tx] = g_a[k0 + i] * W[(size_t)(k0 + i) * Dout + n0 + tx];
    __syncthreads();
    for (int i = ty; i < 32; i += 8) {
        float v = tile[tx][i];
        size_t idx = (size_t)(n0 + i) * Din + (k0 + tx);
        __nv_bfloat16 h = __float2bfloat16(v);
        WTh[idx] = h;
        WTl[idx] = __float2bfloat16(v - __bfloat162float(h));
    }
}

__global__ void rowsq_bf(const __nv_bfloat16* __restrict__ hi,
                         const __nv_bfloat16* __restrict__ lo, int Kd) {
    __shared__ float red[256];
    int row = blockIdx.x, t = threadIdx.x;
    float v = 0.f;
    if (t < Kd) {
        size_t i = (size_t)row * Kd + t;
        v = __bfloat162float(hi[i]) + __bfloat162float(lo[i]);
    }
    red[t] = v * v;
    __syncthreads();
    for (int s = 128; s > 0; s >>= 1) {
        if (t < s) red[t] += red[t + s];
        __syncthreads();
    }
    if (t == 0) g_k2[row] = red[0];
}

// ===========================================================================
// HMMA GEMM (mma.sync m16n8k16 bf16): C = (Ah+Al) @ (Bh+Bl)^T  (3-product)
// A [M,K] row-major hi/lo, B [N,K] row-major hi/lo (i.e. WT or k).
// CTA tile 128x128, K-tile 32, 3-stage cp.async pipeline, 8 warps (2x4),
// warp tile 64x32.
// mode 0: Y = tanh(C + bias2[col]) -> re-split to bf16 hi/lo.
// mode 1: Yf = 2*C - k2[col].
// ===========================================================================
#define LDKB 80                 // smem bytes per row (32 bf16 data + 8 pad)
#define TILE_B (128 * LDKB)     // 10240 B
#define STAGE_B (4 * TILE_B)    // 40960 B (Ah,Al,Bh,Bl)
#define GEMM_SMEM (3 * STAGE_B) // 122880 B

__device__ __forceinline__ void mma_bf16(float* d, const uint32_t* a, const uint32_t* b) {
    asm volatile("mma.sync.aligned.m16n8k16.row.col.f32.bf16.bf16.f32 "
        "{%0,%1,%2,%3}, {%4,%5,%6,%7}, {%8,%9}, {%0,%1,%2,%3};"
        : "+f"(d[0]), "+f"(d[1]), "+f"(d[2]), "+f"(d[3])
        : "r"(a[0]), "r"(a[1]), "r"(a[2]), "r"(a[3]), "r"(b[0]), "r"(b[1]));
}

__global__ __launch_bounds__(256, 1) void gemm_mma(
    const __nv_bfloat16* __restrict__ Ah, const __nv_bfloat16* __restrict__ Al,
    const __nv_bfloat16* __restrict__ Bh, const __nv_bfloat16* __restrict__ Bl,
    int K, int ldOut, int mode,
    __nv_bfloat16* __restrict__ Yh, __nv_bfloat16* __restrict__ Yl,
    float* __restrict__ Yf)
{
    extern __shared__ __align__(16) char smem[];
    const int tid = threadIdx.x;
    const int wid = tid >> 5, lane = tid & 31;
    const int g = lane >> 2;              // 0..7
    const int cc = (lane & 3) * 2;        // 0,2,4,6
    const int wm = wid >> 2, wn = wid & 3; // warp grid 2 x 4
    const int m0 = blockIdx.y * 128, n0 = blockIdx.x * 128;
    const int T = K >> 5;                 // K-tiles of 32

    // ---- async tile fill: 2048 16B chunks/stage, 8 per thread ----
    auto fill = [&](int t, int s) {
        char* base = smem + s * STAGE_B;
        const int k0 = t << 5;
#pragma unroll
        for (int l = 0; l < 8; ++l) {
            int id = tid + (l << 8);
            int which = id >> 9;          // 0:Ah 1:Al 2:Bh 3:Bl
            int e = id & 511;
            int row = e >> 2, c4 = e & 3;
            const __nv_bfloat16* src =
                (which == 0) ? Ah : (which == 1) ? Al : (which == 2) ? Bh : Bl;
            int grow = ((which < 2) ? m0 : n0) + row;
            const char* gp = (const char*)(src + (size_t)grow * K + k0) + (c4 << 4);
            uint32_t sp = (uint32_t)__cvta_generic_to_shared(
                base + which * TILE_B + row * LDKB + (c4 << 4));
            asm volatile("cp.async.cg.shared.global [%0], [%1], 16;" :: "r"(sp), "l"(gp));
        }
        asm volatile("cp.async.commit_group;");
    };

    float acc[4][4][4];
#pragma unroll
    for (int i = 0; i < 4; ++i)
#pragma unroll
        for (int j = 0; j < 4; ++j)
#pragma unroll
            for (int r = 0; r < 4; ++r) acc[i][j][r] = 0.f;

    fill(0, 0);
    if (T > 1) fill(1, 1);

    for (int t = 0; t < T; ++t) {
        if (t + 2 < T) fill(t + 2, (t + 2) % 3);
        int rem = T - 1 - t; if (rem > 2) rem = 2;
        if (rem == 2)      asm volatile("cp.async.wait_group 2;");
        else if (rem == 1) asm volatile("cp.async.wait_group 1;");
        else               asm volatile("cp.async.wait_group 0;");
        __syncthreads();

        const char* st = smem + (t % 3) * STAGE_B;
#pragma unroll
        for (int kk = 0; kk < 2; ++kk) {
            const int kb = (kk << 4) + cc;      // k element offset for this thread
            uint32_t bh[4][2], bl[4][2];
#pragma unroll
            for (int nt = 0; nt < 4; ++nt) {
                const char* pB = st + 2 * TILE_B + (wn * 32 + nt * 8 + g) * LDKB + kb * 2;
                bh[nt][0] = *(const uint32_t*)pB;
                bh[nt][1] = *(const uint32_t*)(pB + 16);
                bl[nt][0] = *(const uint32_t*)(pB + TILE_B);
                bl[nt][1] = *(const uint32_t*)(pB + TILE_B + 16);
            }
#pragma unroll
            for (int mt = 0; mt < 4; ++mt) {
                const char* pA = st + (wm * 64 + mt * 16 + g) * LDKB + kb * 2;
                uint32_t ah[4], al[4];
                ah[0] = *(const uint32_t*)pA;
                ah[1] = *(const uint32_t*)(pA + 8 * LDKB);
                ah[2] = *(const uint32_t*)(pA + 16);
                ah[3] = *(const uint32_t*)(pA + 8 * LDKB + 16);
                al[0] = *(const uint32_t*)(pA + TILE_B);
                al[1] = *(const uint32_t*)(pA + TILE_B + 8 * LDKB);
                al[2] = *(const uint32_t*)(pA + TILE_B + 16);
                al[3] = *(const uint32_t*)(pA + TILE_B + 8 * LDKB + 16);
#pragma unroll
                for (int nt = 0; nt < 4; ++nt) {
                    mma_bf16(acc[mt][nt], ah, bh[nt]);  // hi*hi
                    mma_bf16(acc[mt][nt], ah, bl[nt]);  // hi*lo
                    mma_bf16(acc[mt][nt], al, bh[nt]);  // lo*hi
                }
            }
        }
        __syncthreads();
    }

    // ---- epilogue ----
#pragma unroll
    for (int mt = 0; mt < 4; ++mt) {
#pragma unroll
        for (int nt = 0; nt < 4; ++nt) {
            int row = m0 + wm * 64 + mt * 16 + g;
            int col = n0 + wn * 32 + nt * 8 + cc;
            float* a = acc[mt][nt];
            if (mode == 0) {
                float bA = g_bias2[col], bB = g_bias2[col + 1];
#pragma unroll
                for (int h = 0; h < 2; ++h) {
                    int r = row + h * 8;
                    float v0 = tanhf(a[h * 2 + 0] + bA);
                    float v1 = tanhf(a[h * 2 + 1] + bB);
                    __nv_bfloat162 hp, lp;
                    hp.x = __float2bfloat16(v0);
                    hp.y = __float2bfloat16(v1);
                    lp.x = __float2bfloat16(v0 - __bfloat162float(hp.x));
                    lp.y = __float2bfloat16(v1 - __bfloat162float(hp.y));
                    *(uint32_t*)(Yh + (size_t)r * ldOut + col) = *(uint32_t*)&hp;
                    *(uint32_t*)(Yl + (size_t)r * ldOut + col) = *(uint32_t*)&lp;
                }
            } else {
                float kA = g_k2[col], kB = g_k2[col + 1];
#pragma unroll
                for (int h = 0; h < 2; ++h) {
                    int r = row + h * 8;
                    float2 o;
                    o.x = 2.f * a[h * 2 + 0] - kA;
                    o.y = 2.f * a[h * 2 + 1] - kB;
                    *(float2*)(Yf + (size_t)r * ldOut + col) = o;
                }
            }
        }
    }
}

// ===========================================================================
// softmax + weighted mean + clip
// ===========================================================================
__global__ void softmax_out(const float* __restrict__ sim,
                            const float* __restrict__ y,
                            float* __restrict__ out, int N)
{
    extern __shared__ float srow[];
    __shared__ float red[256];
    int row = blockIdx.x, t = threadIdx.x;
    const float* s = sim + (size_t)row * N;

    float lmax = -3.4e38f;
    for (int j = t; j < N; j += 256) {
        float v = s[j];
        srow[j] = v;
        lmax = fmaxf(lmax, v);
    }
    red[t] = lmax;
    __syncthreads();
    for (int st = 128; st > 0; st >>= 1) {
        if (t < st) red[t] = fmaxf(red[t], red[t + st]);
        __syncthreads();
    }
    float m = red[0];
    __syncthreads();

    float lsum = 0.f, lw = 0.f;
    for (int j = t; j < N; j += 256) {
        float e = __expf(srow[j] - m);
        lsum += e;
        lw = fmaf(e, y[j], lw);
    }
    red[t] = lsum;
    __syncthreads();
    for (int st = 128; st > 0; st >>= 1) {
        if (t < st) red[t] += red[t + st];
        __syncthreads();
    }
    float tot = red[0];
    __syncthreads();
    red[t] = lw;
    __syncthreads();
    for (int st = 128; st > 0; st >>= 1) {
        if (t < st) red[t] += red[t + st];
        __syncthreads();
    }
    if (t == 0) {
        float r = red[0] / tot;
        out[row] = fminf(fmaxf(r, 0.f), 1.f);
    }
}

// ===========================================================================
// Host launcher
// ===========================================================================
extern "C" void kernel_launch(void* const* d_in, const int* in_sizes, int n_in,
                              void* d_out, int out_size)
{
    const float* x   = (const float*)d_in[0];
    const float* xn  = (const float*)d_in[1];
    const float* y   = (const float*)d_in[2];
    const float* W1  = (const float*)d_in[3];
    const float* b1  = (const float*)d_in[4];
    const float* gm1 = (const float*)d_in[5];
    const float* be1 = (const float*)d_in[6];
    const float* W2  = (const float*)d_in[7];
    const float* b2  = (const float*)d_in[8];
    const float* gm2 = (const float*)d_in[9];
    const float* be2 = (const float*)d_in[10];
    const float* W3  = (const float*)d_in[11];
    const float* b3  = (const float*)d_in[12];
    const float* gm3 = (const float*)d_in[13];
    const float* be3 = (const float*)d_in[14];

    const int D  = in_sizes[5];          // 1024
    const int B  = in_sizes[0] / D;      // 4096
    const int N  = in_sizes[2];          // 8192
    const int D1 = in_sizes[4];          // 1024
    const int D2 = in_sizes[8];          // 512
    const int D3 = in_sizes[12];         // 256

    __nv_bfloat16 *p1h, *p1l, *p2h, *p2l, *wth, *wtl, *qh, *ql, *kh, *kl;
    float* simp;
    cudaGetSymbolAddress((void**)&p1h, g_P1h); cudaGetSymbolAddress((void**)&p1l, g_P1l);
    cudaGetSymbolAddress((void**)&p2h, g_P2h); cudaGetSymbolAddress((void**)&p2l, g_P2l);
    cudaGetSymbolAddress((void**)&wth, g_WTh); cudaGetSymbolAddress((void**)&wtl, g_WTl);
    cudaGetSymbolAddress((void**)&qh, g_qh);   cudaGetSymbolAddress((void**)&ql, g_ql);
    cudaGetSymbolAddress((void**)&kh, g_kh);   cudaGetSymbolAddress((void**)&kl, g_kl);
    cudaGetSymbolAddress((void**)&simp, g_sim);

    cudaFuncSetAttribute(gemm_mma, cudaFuncAttributeMaxDynamicSharedMemorySize, GEMM_SMEM);

    auto run_layer = [&](const __nv_bfloat16* Ah, const __nv_bfloat16* Al,
                         const float* Xf32, int R, int Din, int Dout,
                         const float* W, const float* b,
                         const float* gam, const float* bet,
                         __nv_bfloat16* Yh, __nv_bfloat16* Yl) {
        zero_stats<<<(Din + 255) / 256, 256>>>(Din);
        if (Xf32)
            colstats<<<dim3((Din + 255) / 256, 32), 256>>>(Xf32, R, Din);
        else
            colstats_bf<<<dim3((Din + 255) / 256, 32), 256>>>(Ah, Al, R, Din);
        finalize_stats<<<(Din + 255) / 256, 256>>>(R, Din, gam, bet);
        init_bias2<<<(Dout + 255) / 256, 256>>>(b, Dout);
        bias2acc<<<dim3(Dout / 128, Din / 128), 128>>>(W, Din, Dout);
        wprep<<<dim3(Dout / 32, Din / 32), dim3(32, 8)>>>(W, Din, Dout, wth, wtl);
        gemm_mma<<<dim3(Dout / 128, R / 128), 256, GEMM_SMEM>>>(
            Ah, Al, wth, wtl, Din, Dout, 0, Yh, Yl, nullptr);
    };

    // ---- q branch ----
    splitf<<<(B * D + 255) / 256, 256>>>(x, p1h, p1l, B * D);
    run_layer(p1h, p1l, x,       B, D,  D1, W1, b1, gm1, be1, p2h, p2l);
    run_layer(p2h, p2l, nullptr, B, D1, D2, W2, b2, gm2, be2, p1h, p1l);
    run_layer(p1h, p1l, nullptr, B, D2, D3, W3, b3, gm3, be3, qh, ql);

    // ---- k branch ----
    splitf<<<(N * D + 255) / 256, 256>>>(xn, p1h, p1l, N * D);
    run_layer(p1h, p1l, xn,      N, D,  D1, W1, b1, gm1, be1, p2h, p2l);
    run_layer(p2h, p2l, nullptr, N, D1, D2, W2, b2, gm2, be2, p1h, p1l);
    run_layer(p1h, p1l, nullptr, N, D2, D3, W3, b3, gm3, be3, kh, kl);

    // ---- similarity + softmax ----
    rowsq_bf<<<N, 256>>>(kh, kl, D3);
    gemm_mma<<<dim3(N / 128, B / 128), 256, GEMM_SMEM>>>(
        qh, ql, kh, kl, D3, N, 1, nullptr, nullptr, simp);
    softmax_out<<<B, 256, N * sizeof(float)>>>(simp, y, (float*)d_out, N);
}

// round 4
// speedup vs baseline: 2.4211x; 1.3725x over previous
#include <cuda_runtime.h>
#include <cuda_bf16.h>
#include <math.h>
#include <stdint.h>

// ===========================================================================
// Static scratch (B=4096, N=8192, D<=1024 fixed by dataset)
// ===========================================================================
__device__ float g_sum[1024];
__device__ float g_sumsq[1024];
__device__ float g_a[1024];
__device__ float g_dd[1024];
__device__ float g_bias2[1024];
__device__ float g_k2[8192];
__device__ __nv_bfloat16 g_P1h[8192 * 1024], g_P1l[8192 * 1024];
__device__ __nv_bfloat16 g_P2h[8192 * 1024], g_P2l[8192 * 1024];
__device__ __nv_bfloat16 g_WTh[1024 * 1024], g_WTl[1024 * 1024];
__device__ __nv_bfloat16 g_qh[4096 * 256], g_ql[4096 * 256];
__device__ __nv_bfloat16 g_kh[8192 * 256], g_kl[8192 * 256];
__device__ float g_sim[(size_t)4096 * 8192];

// ===========================================================================
// Prep kernels (fused where possible)
// ===========================================================================
__global__ void zero_two(float* a, float* b, int n) {
    int i = blockIdx.x * blockDim.x + threadIdx.x;
    if (i < n) { a[i] = 0.f; b[i] = 0.f; }
}
__global__ void zero_one(float* a, int n) {
    int i = blockIdx.x * blockDim.x + threadIdx.x;
    if (i < n) a[i] = 0.f;
}

// fp32 -> bf16 hi/lo split + column stats accumulation (layer-1 input)
__global__ void split_stats(const float* __restrict__ X,
                            __nv_bfloat16* __restrict__ hi,
                            __nv_bfloat16* __restrict__ lo,
                            int R, int Din) {
    int c = blockIdx.x * blockDim.x + threadIdx.x;
    if (c >= Din) return;
    int chunk = R / gridDim.y;
    int r0 = blockIdx.y * chunk;
    float s = 0.f, s2 = 0.f;
    for (int r = r0; r < r0 + chunk; ++r) {
        size_t i = (size_t)r * Din + c;
        float v = X[i];
        __nv_bfloat16 h = __float2bfloat16(v);
        hi[i] = h;
        lo[i] = __float2bfloat16(v - __bfloat162float(h));
        s += v;
        s2 = fmaf(v, v, s2);
    }
    atomicAdd(&g_sum[c], s);
    atomicAdd(&g_sumsq[c], s2);
}

// finalize BN stats (Din) + init bias2 (Dout), one kernel
__global__ void finalize_bias(int R, int Din, int Dout,
                              const float* __restrict__ gam,
                              const float* __restrict__ bet,
                              const float* __restrict__ b) {
    int c = blockIdx.x * blockDim.x + threadIdx.x;
    if (c < Din) {
        float inv = 1.0f / (float)R;
        float mean = g_sum[c] * inv;
        float var = g_sumsq[c] * inv - mean * mean;
        float a = gam[c] * rsqrtf(var + 1e-5f);
        g_a[c] = a;
        g_dd[c] = bet[c] - mean * a;
    }
    if (c < Dout) g_bias2[c] = b[c];
}

// WT[n,k] = a[k]*W[k,n] split to bf16 hi/lo (transpose), fused with
// bias2[n] += sum_k dd[k]*W[k,n]. 32x32 tiles, 32x8 threads.
__global__ void wprep_bias(const float* __restrict__ W, int Din, int Dout,
                           __nv_bfloat16* __restrict__ WTh,
                           __nv_bfloat16* __restrict__ WTl) {
    __shared__ float tile[32][33];
    __shared__ float sbias[8][32];
    int k0 = blockIdx.y * 32, n0 = blockIdx.x * 32;
    int tx = threadIdx.x, ty = threadIdx.y;
    float bp = 0.f;
    for (int i = ty; i < 32; i += 8) {
        float w = W[(size_t)(k0 + i) * Dout + n0 + tx];
        tile[i][tx] = g_a[k0 + i] * w;
        bp = fmaf(g_dd[k0 + i], w, bp);
    }
    sbias[ty][tx] = bp;
    __syncthreads();
    if (ty == 0) {
        float s = 0.f;
#pragma unroll
        for (int j = 0; j < 8; ++j) s += sbias[j][tx];
        atomicAdd(&g_bias2[n0 + tx], s);
    }
    for (int i = ty; i < 32; i += 8) {
        float v = tile[tx][i];
        size_t idx = (size_t)(n0 + i) * Din + (k0 + tx);
        __nv_bfloat16 h = __float2bfloat16(v);
        WTh[idx] = h;
        WTl[idx] = __float2bfloat16(v - __bfloat162float(h));
    }
}

// ===========================================================================
// HMMA GEMM (mma.sync m16n8k16 bf16): C = (Ah+Al) @ (Bh+Bl)^T  (3-product)
// CTA tile 128x128, K-tile 32, 2-stage cp.async pipeline, 8 warps (2x4),
// warp tile 64x32, 2 CTAs/SM.
// mode 0: Y = tanh(C + bias2[col]) -> split bf16 hi/lo.
//         accum 1: also accumulate column sum/sumsq of tanh into g_sum/g_sumsq
//         accum 2: also accumulate row sum of tanh^2 into g_k2
// mode 1: Yf = 2*C - k2[col].
// ===========================================================================
#define LDKB 80                 // smem bytes per row (32 bf16 + 8B pad)
#define TILE_B (128 * LDKB)     // 10240 B
#define STAGE_B (4 * TILE_B)    // 40960 B (Ah,Al,Bh,Bl)
#define GEMM_SMEM (2 * STAGE_B) // 81920 B

__device__ __forceinline__ void mma_bf16(float* d, const uint32_t* a, const uint32_t* b) {
    asm volatile("mma.sync.aligned.m16n8k16.row.col.f32.bf16.bf16.f32 "
        "{%0,%1,%2,%3}, {%4,%5,%6,%7}, {%8,%9}, {%0,%1,%2,%3};"
        : "+f"(d[0]), "+f"(d[1]), "+f"(d[2]), "+f"(d[3])
        : "r"(a[0]), "r"(a[1]), "r"(a[2]), "r"(a[3]), "r"(b[0]), "r"(b[1]));
}

__global__ __launch_bounds__(256, 2) void gemm_mma(
    const __nv_bfloat16* __restrict__ Ah, const __nv_bfloat16* __restrict__ Al,
    const __nv_bfloat16* __restrict__ Bh, const __nv_bfloat16* __restrict__ Bl,
    int K, int ldOut, int mode, int accum,
    __nv_bfloat16* __restrict__ Yh, __nv_bfloat16* __restrict__ Yl,
    float* __restrict__ Yf)
{
    extern __shared__ __align__(16) char smem[];
    const int tid = threadIdx.x;
    const int wid = tid >> 5, lane = tid & 31;
    const int g = lane >> 2;               // 0..7
    const int cc = (lane & 3) * 2;         // 0,2,4,6
    const int wm = wid >> 2, wn = wid & 3; // warp grid 2 x 4
    const int m0 = blockIdx.y * 128, n0 = blockIdx.x * 128;
    const int T = K >> 5;                  // K-tiles of 32

    auto fill = [&](int t, int s) {
        char* base = smem + s * STAGE_B;
        const int k0 = t << 5;
#pragma unroll
        for (int l = 0; l < 8; ++l) {
            int id = tid + (l << 8);
            int which = id >> 9;           // 0:Ah 1:Al 2:Bh 3:Bl
            int e = id & 511;
            int row = e >> 2, c4 = e & 3;
            const __nv_bfloat16* src =
                (which == 0) ? Ah : (which == 1) ? Al : (which == 2) ? Bh : Bl;
            int grow = ((which < 2) ? m0 : n0) + row;
            const char* gp = (const char*)(src + (size_t)grow * K + k0) + (c4 << 4);
            uint32_t sp = (uint32_t)__cvta_generic_to_shared(
                base + which * TILE_B + row * LDKB + (c4 << 4));
            asm volatile("cp.async.cg.shared.global [%0], [%1], 16;" :: "r"(sp), "l"(gp));
        }
        asm volatile("cp.async.commit_group;");
    };

    float acc[4][4][4];
#pragma unroll
    for (int i = 0; i < 4; ++i)
#pragma unroll
        for (int j = 0; j < 4; ++j)
#pragma unroll
            for (int r = 0; r < 4; ++r) acc[i][j][r] = 0.f;

    fill(0, 0);

    for (int t = 0; t < T; ++t) {
        if (t + 1 < T) {
            fill(t + 1, (t + 1) & 1);
            asm volatile("cp.async.wait_group 1;");
        } else {
            asm volatile("cp.async.wait_group 0;");
        }
        __syncthreads();

        const char* st = smem + (t & 1) * STAGE_B;
#pragma unroll
        for (int kk = 0; kk < 2; ++kk) {
            const int kb = (kk << 4) + cc;
            uint32_t bh[4][2], bl[4][2];
#pragma unroll
            for (int nt = 0; nt < 4; ++nt) {
                const char* pB = st + 2 * TILE_B + (wn * 32 + nt * 8 + g) * LDKB + kb * 2;
                bh[nt][0] = *(const uint32_t*)pB;
                bh[nt][1] = *(const uint32_t*)(pB + 16);
                bl[nt][0] = *(const uint32_t*)(pB + TILE_B);
                bl[nt][1] = *(const uint32_t*)(pB + TILE_B + 16);
            }
#pragma unroll
            for (int mt = 0; mt < 4; ++mt) {
                const char* pA = st + (wm * 64 + mt * 16 + g) * LDKB + kb * 2;
                uint32_t ah[4], al[4];
                ah[0] = *(const uint32_t*)pA;
                ah[1] = *(const uint32_t*)(pA + 8 * LDKB);
                ah[2] = *(const uint32_t*)(pA + 16);
                ah[3] = *(const uint32_t*)(pA + 8 * LDKB + 16);
                al[0] = *(const uint32_t*)(pA + TILE_B);
                al[1] = *(const uint32_t*)(pA + TILE_B + 8 * LDKB);
                al[2] = *(const uint32_t*)(pA + TILE_B + 16);
                al[3] = *(const uint32_t*)(pA + TILE_B + 8 * LDKB + 16);
#pragma unroll
                for (int nt = 0; nt < 4; ++nt) {
                    mma_bf16(acc[mt][nt], ah, bh[nt]);  // hi*hi
                    mma_bf16(acc[mt][nt], ah, bl[nt]);  // hi*lo
                    mma_bf16(acc[mt][nt], al, bh[nt]);  // lo*hi
                }
            }
        }
        __syncthreads();
    }

    // ---- epilogue (smem pipeline area reusable after last sync) ----
    float* s_sum = (float*)smem;          // 128 floats
    float* s_sq  = (float*)smem + 128;    // 128 floats (cols) or rows for accum 2
    if (accum) {
        if (tid < 128) { s_sum[tid] = 0.f; s_sq[tid] = 0.f; }
        __syncthreads();
    }

#pragma unroll
    for (int mt = 0; mt < 4; ++mt) {
#pragma unroll
        for (int nt = 0; nt < 4; ++nt) {
            int row = m0 + wm * 64 + mt * 16 + g;
            int col = n0 + wn * 32 + nt * 8 + cc;
            float* a = acc[mt][nt];
            if (mode == 0) {
                float bA = g_bias2[col], bB = g_bias2[col + 1];
#pragma unroll
                for (int h = 0; h < 2; ++h) {
                    int r = row + h * 8;
                    float v0 = tanhf(a[h * 2 + 0] + bA);
                    float v1 = tanhf(a[h * 2 + 1] + bB);
                    a[h * 2 + 0] = v0;   // keep for stats
                    a[h * 2 + 1] = v1;
                    __nv_bfloat162 hp, lp;
                    hp.x = __float2bfloat16(v0);
                    hp.y = __float2bfloat16(v1);
                    lp.x = __float2bfloat16(v0 - __bfloat162float(hp.x));
                    lp.y = __float2bfloat16(v1 - __bfloat162float(hp.y));
                    *(uint32_t*)(Yh + (size_t)r * ldOut + col) = *(uint32_t*)&hp;
                    *(uint32_t*)(Yl + (size_t)r * ldOut + col) = *(uint32_t*)&lp;
                }
            } else {
                float kA = g_k2[col], kB = g_k2[col + 1];
#pragma unroll
                for (int h = 0; h < 2; ++h) {
                    int r = row + h * 8;
                    float2 o;
                    o.x = 2.f * a[h * 2 + 0] - kA;
                    o.y = 2.f * a[h * 2 + 1] - kB;
                    *(float2*)(Yf + (size_t)r * ldOut + col) = o;
                }
            }
        }
    }

    if (accum == 1) {
        // column stats of tanh values (local col index = wn*32+nt*8+cc)
#pragma unroll
        for (int nt = 0; nt < 4; ++nt) {
            int lc = wn * 32 + nt * 8 + cc;
            float s0 = 0.f, q0 = 0.f, s1 = 0.f, q1 = 0.f;
#pragma unroll
            for (int mt = 0; mt < 4; ++mt) {
                float* a = acc[mt][nt];
#pragma unroll
                for (int h = 0; h < 2; ++h) {
                    s0 += a[h * 2 + 0]; q0 = fmaf(a[h * 2 + 0], a[h * 2 + 0], q0);
                    s1 += a[h * 2 + 1]; q1 = fmaf(a[h * 2 + 1], a[h * 2 + 1], q1);
                }
            }
            atomicAdd(&s_sum[lc], s0);     atomicAdd(&s_sq[lc], q0);
            atomicAdd(&s_sum[lc + 1], s1); atomicAdd(&s_sq[lc + 1], q1);
        }
        __syncthreads();
        if (tid < 128) {
            atomicAdd(&g_sum[n0 + tid], s_sum[tid]);
            atomicAdd(&g_sumsq[n0 + tid], s_sq[tid]);
        }
    } else if (accum == 2) {
        // row sumsq of tanh values -> g_k2 (local row = wm*64+mt*16+g+h*8)
#pragma unroll
        for (int mt = 0; mt < 4; ++mt) {
#pragma unroll
            for (int h = 0; h < 2; ++h) {
                int lr = wm * 64 + mt * 16 + g + h * 8;
                float s = 0.f;
#pragma unroll
                for (int nt = 0; nt < 4; ++nt) {
                    float v0 = acc[mt][nt][h * 2 + 0];
                    float v1 = acc[mt][nt][h * 2 + 1];
                    s = fmaf(v0, v0, s);
                    s = fmaf(v1, v1, s);
                }
                atomicAdd(&s_sum[lr], s);
            }
        }
        __syncthreads();
        if (tid < 128) atomicAdd(&g_k2[m0 + tid], s_sum[tid]);
    }
}

// ===========================================================================
// softmax + weighted mean + clip
// ===========================================================================
__global__ void softmax_out(const float* __restrict__ sim,
                            const float* __restrict__ y,
                            float* __restrict__ out, int N)
{
    extern __shared__ float srow[];
    __shared__ float red[256];
    int row = blockIdx.x, t = threadIdx.x;
    const float* s = sim + (size_t)row * N;

    float lmax = -3.4e38f;
    for (int j = t; j < N; j += 256) {
        float v = s[j];
        srow[j] = v;
        lmax = fmaxf(lmax, v);
    }
    red[t] = lmax;
    __syncthreads();
    for (int st = 128; st > 0; st >>= 1) {
        if (t < st) red[t] = fmaxf(red[t], red[t + st]);
        __syncthreads();
    }
    float m = red[0];
    __syncthreads();

    float lsum = 0.f, lw = 0.f;
    for (int j = t; j < N; j += 256) {
        float e = __expf(srow[j] - m);
        lsum += e;
        lw = fmaf(e, y[j], lw);
    }
    red[t] = lsum;
    __syncthreads();
    for (int st = 128; st > 0; st >>= 1) {
        if (t < st) red[t] += red[t + st];
        __syncthreads();
    }
    float tot = red[0];
    __syncthreads();
    red[t] = lw;
    __syncthreads();
    for (int st = 128; st > 0; st >>= 1) {
        if (t < st) red[t] += red[t + st];
        __syncthreads();
    }
    if (t == 0) {
        float r = red[0] / tot;
        out[row] = fminf(fmaxf(r, 0.f), 1.f);
    }
}

// ===========================================================================
// Host launcher
// ===========================================================================
extern "C" void kernel_launch(void* const* d_in, const int* in_sizes, int n_in,
                              void* d_out, int out_size)
{
    const float* x   = (const float*)d_in[0];
    const float* xn  = (const float*)d_in[1];
    const float* y   = (const float*)d_in[2];
    const float* Ws[3] = {(const float*)d_in[3], (const float*)d_in[7], (const float*)d_in[11]};
    const float* bs[3] = {(const float*)d_in[4], (const float*)d_in[8], (const float*)d_in[12]};
    const float* gs[3] = {(const float*)d_in[5], (const float*)d_in[9], (const float*)d_in[13]};
    const float* es[3] = {(const float*)d_in[6], (const float*)d_in[10], (const float*)d_in[14]};

    const int D  = in_sizes[5];          // 1024
    const int B  = in_sizes[0] / D;      // 4096
    const int N  = in_sizes[2];          // 8192
    const int dims[4] = {D, in_sizes[4], in_sizes[8], in_sizes[12]}; // 1024,1024,512,256

    __nv_bfloat16 *p1h, *p1l, *p2h, *p2l, *wth, *wtl, *qh, *ql, *kh, *kl;
    float *simp, *gsum, *gsumsq, *gk2;
    cudaGetSymbolAddress((void**)&p1h, g_P1h); cudaGetSymbolAddress((void**)&p1l, g_P1l);
    cudaGetSymbolAddress((void**)&p2h, g_P2h); cudaGetSymbolAddress((void**)&p2l, g_P2l);
    cudaGetSymbolAddress((void**)&wth, g_WTh); cudaGetSymbolAddress((void**)&wtl, g_WTl);
    cudaGetSymbolAddress((void**)&qh, g_qh);   cudaGetSymbolAddress((void**)&ql, g_ql);
    cudaGetSymbolAddress((void**)&kh, g_kh);   cudaGetSymbolAddress((void**)&kl, g_kl);
    cudaGetSymbolAddress((void**)&simp, g_sim);
    cudaGetSymbolAddress((void**)&gsum, g_sum);
    cudaGetSymbolAddress((void**)&gsumsq, g_sumsq);
    cudaGetSymbolAddress((void**)&gk2, g_k2);

    cudaFuncSetAttribute(gemm_mma, cudaFuncAttributeMaxDynamicSharedMemorySize, GEMM_SMEM);

    // run one branch (R rows). outputs of layers ping-pong p2 -> p1 -> final
    auto run_branch = [&](const float* X, int R,
                          __nv_bfloat16* outh, __nv_bfloat16* outl, int last_accum) {
        zero_two<<<4, 256>>>(gsum, gsumsq, dims[0]);
        split_stats<<<dim3(dims[0] / 256, 64), 256>>>(X, p1h, p1l, R, dims[0]);

        __nv_bfloat16* ih = p1h; __nv_bfloat16* il = p1l;
        __nv_bfloat16* oh = p2h; __nv_bfloat16* ol = p2l;
        for (int i = 0; i < 3; ++i) {
            int Din = dims[i], Dout = dims[i + 1];
            finalize_bias<<<(Din > Dout ? Din : Dout + 255) / 256 + 1, 256>>>(
                R, Din, Dout, gs[i], es[i], bs[i]);
            wprep_bias<<<dim3(Dout / 32, Din / 32), dim3(32, 8)>>>(Ws[i], Din, Dout, wth, wtl);
            int accum = (i < 2) ? 1 : last_accum;
            if (accum == 1) zero_two<<<(Dout + 255) / 256, 256>>>(gsum, gsumsq, Dout);
            __nv_bfloat16* th = (i == 2) ? outh : oh;
            __nv_bfloat16* tl = (i == 2) ? outl : ol;
            gemm_mma<<<dim3(Dout / 128, R / 128), 256, GEMM_SMEM>>>(
                ih, il, wth, wtl, Din, Dout, 0, accum, th, tl, nullptr);
            __nv_bfloat16* sh = ih; __nv_bfloat16* sl = il;
            ih = oh; il = ol; oh = sh; ol = sl;
        }
    };

    run_branch(x, B, qh, ql, 0);
    zero_one<<<(N + 255) / 256, 256>>>(gk2, N);
    run_branch(xn, N, kh, kl, 2);   // layer-3 epilogue accumulates g_k2

    gemm_mma<<<dim3(N / 128, B / 128), 256, GEMM_SMEM>>>(
        qh, ql, kh, kl, dims[3], N, 1, 0, nullptr, nullptr, simp);
    softmax_out<<<B, 256, N * sizeof(float)>>>(simp, y, (float*)d_out, N);
}